// round 10
// baseline (speedup 1.0000x reference)
#include <cuda_runtime.h>

// Problem constants (fixed by reference)
#define BS   1024
#define NSEQ 32
#define NBOX 128
#define NCTX 5
#define MAXC 4

// Fused kernel (R8 structure):
//  - Warps [0, n_tasks): one per (it,b) task; if pval>0, compute the updated
//    parent row and write it to out.
//  - Warps [n_tasks, n_tasks + BS*NSEQ): one per (b,r) row; copy if r is not
//    a valid parent (parent rows written exclusively by compute warps).
// Fully parallel: children always have larger indices than parents; parents
// ascend & are unique per batch, so every read sees the ORIGINAL ent_attn.
//
// NEW in this round: the spo/roi row reduction uses a truly COALESCED layout
// (f4[j*32+lane], nL=4 lines per LDG.128) instead of lane-contiguous chunks
// (nL=20). The box/ctx demux for element e=128j+4l+m uses a shared-staged
// child row (caS[e/5]) and a mod-5 lane-rotation trick so all accumulator
// indices stay compile-time.
__global__ __launch_bounds__(256, 5) void topdown_fused_kernel(
    const float* __restrict__ ent,   // [BS,NSEQ,NBOX]
    const float* __restrict__ spo,   // [BS,NSEQ,NBOX,NCTX]
    const int*   __restrict__ ctx,   // [BS,NSEQ,NBOX,NCTX]
    const float* __restrict__ roi,   // [BS,NSEQ,NBOX,NCTX]
    const int*   __restrict__ rcls,  // [BS,NBOX]
    const float* __restrict__ w,     // [BS,NSEQ,NBOX]
    const int*   __restrict__ pidx,  // [L,BS]
    const float* __restrict__ pval,  // [L,BS]
    const int*   __restrict__ cidx,  // [L,BS,MAXC]
    const float* __restrict__ cval,  // [L,BS,MAXC]
    const int*   __restrict__ eidx,  // [L,BS,MAXC]
    const int*   __restrict__ fsmp,  // [L,BS]
    const int*   __restrict__ fslt,  // [L,BS]
    float*       __restrict__ out,   // [BS,NSEQ,NBOX]
    int n_tasks, int L)
{
    __shared__ float caS[8][NBOX];   // per-warp staged child row * cls mask

    const int gwarp = (blockIdx.x * blockDim.x + threadIdx.x) >> 5;
    const int lane  = threadIdx.x & 31;

    if (gwarp >= n_tasks) {
        // ---------------- copy warp: one per (b, r) row (as in R8) ----------------
        const int idx = gwarp - n_tasks;
        if (idx >= BS * NSEQ) return;
        const int b = idx >> 5;          // / NSEQ
        const int r = idx & (NSEQ - 1);  // % NSEQ

        int   p = -1;
        float v = 0.f;
        if (lane < L) {
            p = pidx[lane * BS + b];
            v = pval[lane * BS + b];
        }
        const unsigned m =
            __ballot_sync(0xffffffffu, (lane < L) && (v > 0.f) && (p == r));
        if (m) return;  // compute warp owns this row

        const float4* src = (const float4*)(ent + ((size_t)b * NSEQ + r) * NBOX);
        float4*       dst = (float4*)(out + ((size_t)b * NSEQ + r) * NBOX);
        const float4 val = __ldcs(src + lane);
        __stcs(dst + lane, val);
        return;
    }

    // ---------------- compute warp: one per (it, b) task ----------------
    const int task = gwarp;
    const int it = task >> 10;          // / BS
    const int b  = task & (BS - 1);     // % BS

    const int base = it * BS + b;
    const float pv = pval[base];
    if (pv <= 0.f) return;
    const int r = pidx[base];

    const int   c0  = cidx[base * MAXC + 0];
    const float cv0 = cval[base * MAXC + 0];
    const int   e0  = eidx[base * MAXC + 0];
    const int   fs  = fsmp[base];
    const int   fl  = fslt[base];
    const int   fe  = eidx[(it * BS + fs) * MAXC + fl];

    const int wslot = (threadIdx.x >> 5) & 7;
    const int* clsrow = rcls + (size_t)b * NBOX;

    // stage child row * cls into shared (lane owns boxes 4l..4l+3)
    const float4 ecv = ((const float4*)(ent + ((size_t)b * NSEQ + c0) * NBOX))[lane];
    const int4   cl  = ((const int4*)clsrow)[lane];
    {
        float4 cav;
        cav.x = (cl.x == -1) ? 0.f : ecv.x;
        cav.y = (cl.y == -1) ? 0.f : ecv.y;
        cav.z = (cl.z == -1) ? 0.f : ecv.z;
        cav.w = (cl.w == -1) ? 0.f : ecv.w;
        ((float4*)caS[wslot])[lane] = cav;
    }
    __syncwarp();

    // --- coalesced row loads: instruction j covers bytes [512j, 512j+512) ---
    const float4* spoV = (const float4*)(spo + ((size_t)b * NSEQ + e0) * NBOX * NCTX);
    const float4* roiV = (const float4*)(roi + ((size_t)b * NSEQ + e0) * NBOX * NCTX);
    float4 sv[5], mv[5];
    #pragma unroll
    for (int j = 0; j < 5; j++) sv[j] = __ldcs(spoV + j * 32 + lane);
    #pragma unroll
    for (int j = 0; j < 5; j++) mv[j] = __ldcs(roiV + j * 32 + lane);

    // element e = 128j + 4*lane + m : box = e/5, k = e%5 = ((3j+m) + 4*lane) mod 5.
    // Accumulate into u[(3j+m)%5] (compile-time); un-rotate by lane afterwards.
    float u[5] = {0.f, 0.f, 0.f, 0.f, 0.f};
    const unsigned el = 4u * (unsigned)lane;
    #define TERM(j, m, S, M)                                              \
        { unsigned e = el + (128u * (j) + (m));                           \
          u[(3 * (j) + (m)) % 5] += caS[wslot][e / 5u] * (S) * (M); }
    #pragma unroll
    for (int j = 0; j < 5; j++) {
        TERM(j, 0, sv[j].x, mv[j].x)
        TERM(j, 1, sv[j].y, mv[j].y)
        TERM(j, 2, sv[j].z, mv[j].z)
        TERM(j, 3, sv[j].w, mv[j].w)
    }
    #undef TERM

    // un-rotate: true-k bucket v[k] = u[(k + lane) % 5]
    const int lm5 = lane % 5;
    float vv[5];
    #pragma unroll
    for (int k = 0; k < 5; k++) {
        int idx = lm5 + k;
        if (idx >= 5) idx -= 5;
        vv[k] = (idx == 0) ? u[0] : (idx == 1) ? u[1] : (idx == 2) ? u[2]
              : (idx == 3) ? u[3] : u[4];
    }

    #pragma unroll
    for (int o = 16; o > 0; o >>= 1) {
        vv[0] += __shfl_xor_sync(0xffffffffu, vv[0], o);
        vv[1] += __shfl_xor_sync(0xffffffffu, vv[1], o);
        vv[2] += __shfl_xor_sync(0xffffffffu, vv[2], o);
        vv[3] += __shfl_xor_sync(0xffffffffu, vv[3], o);
        vv[4] += __shfl_xor_sync(0xffffffffu, vv[4], o);
    }
    float tr[NCTX];
    #pragma unroll
    for (int k = 0; k < NCTX; k++) tr[k] = cv0 * vv[k] + 1e-6f;

    // scatter columns: ctx_idx_adjusted[fs, fe, box=0, k] (uniform loads)
    int cols[NCTX];
    const int* cbase = ctx + (((size_t)fs * NSEQ + fe) * NBOX) * NCTX;
    #pragma unroll
    for (int k = 0; k < NCTX; k++) cols[k] = cbase[k];

    // --- row update: each lane owns 4 consecutive boxes of the parent row ---
    const float4 sub = ((const float4*)(ent + ((size_t)b * NSEQ + r) * NBOX))[lane];
    const float4 wv  = __ldcs(((const float4*)(w + ((size_t)b * NSEQ + r) * NBOX)) + lane);

    float su[4]  = {sub.x, sub.y, sub.z, sub.w};
    float wa[4]  = {wv.x, wv.y, wv.z, wv.w};
    int   cla[4] = {cl.x, cl.y, cl.z, cl.w};

    float uu[4];
    float mx = 0.f;
    #pragma unroll
    for (int q = 0; q < 4; q++) {
        const int box = lane * 4 + q;
        float add = 1e-6f;
        #pragma unroll
        for (int k = 0; k < NCTX; k++)
            if (cols[k] == box) add = tr[k];
        uu[q] = su[q] + add * wa[q];
        mx = fmaxf(mx, fabsf(uu[q]));
    }
    #pragma unroll
    for (int o = 16; o > 0; o >>= 1)
        mx = fmaxf(mx, __shfl_xor_sync(0xffffffffu, mx, o));
    const float d = (mx <= 1.f) ? 1.f : mx;

    float rr[4];
    #pragma unroll
    for (int q = 0; q < 4; q++) {
        float vvv = uu[q] / d;
        if (cla[q] == -1) vvv = -1.0f;
        rr[q] = vvv;
    }
    float4 res;
    res.x = rr[0]; res.y = rr[1]; res.z = rr[2]; res.w = rr[3];
    __stcs(((float4*)(out + ((size_t)b * NSEQ + r) * NBOX)) + lane, res);
}

extern "C" void kernel_launch(void* const* d_in, const int* in_sizes, int n_in,
                              void* d_out, int out_size) {
    const float* ent  = (const float*)d_in[0];   // ent_attn
    const float* spo  = (const float*)d_in[1];   // spo_attn
    const int*   ctx  = (const int*)  d_in[2];   // ctx_idx_adjusted
    const float* roi  = (const float*)d_in[3];   // roi_mask
    const int*   rcls = (const int*)  d_in[4];   // roi_cls
    const float* w    = (const float*)d_in[5];   // weight_on_children
    const int*   pidx = (const int*)  d_in[6];   // parent_idx [L,BS]
    const float* pval = (const float*)d_in[7];   // parent_valid
    const int*   cidx = (const int*)  d_in[8];   // child_idx
    const float* cval = (const float*)d_in[9];   // child_valid
    const int*   eidx = (const int*)  d_in[10];  // edge_idx
    const int*   fsmp = (const int*)  d_in[11];  // flat_sample
    const int*   fslt = (const int*)  d_in[12];  // flat_slot

    const int L = in_sizes[6] / BS;
    const int n_tasks = L * BS;

    const int total_warps = n_tasks + BS * NSEQ;  // compute + copy warps
    const int threads = 256;                      // 8 warps/block
    const int blocks = (total_warps * 32 + threads - 1) / threads;

    topdown_fused_kernel<<<blocks, threads>>>(
        ent, spo, ctx, roi, rcls, w,
        pidx, pval, cidx, cval, eidx, fsmp, fslt,
        (float*)d_out, n_tasks, L);
}

// round 12
// speedup vs baseline: 1.1001x; 1.1001x over previous
#include <cuda_runtime.h>

// Problem constants (fixed by reference)
#define BS   1024
#define NSEQ 32
#define NBOX 128
#define NCTX 5
#define MAXC 4

// Fused kernel, R8 bodies, NEW role striping:
//   gwarp % 3 == 0 -> compute warp for task gwarp/3   (one per (it,b), pval>0)
//   gwarp % 3 != 0 -> copy warp for row 2*(gwarp/3) + (role-1)
// Ratio 1:2 matches n_tasks : BS*NSEQ (16384 : 32768), so every block mixes
// ~2.7 compute + ~5.3 copy warps -> uniform block durations; copy-warp loads
// backfill compute-warp scoreboard stalls on the same SM throughout the run.
//
// Fully parallel: children always have larger indices than parents; parents
// ascend & are unique per batch, so every read in the sequential reference
// sees the ORIGINAL ent_attn. Parent rows are written only by compute warps,
// non-parent rows only by copy warps (exactly once each).
__global__ __launch_bounds__(256) void topdown_fused_kernel(
    const float* __restrict__ ent,   // [BS,NSEQ,NBOX]
    const float* __restrict__ spo,   // [BS,NSEQ,NBOX,NCTX]
    const int*   __restrict__ ctx,   // [BS,NSEQ,NBOX,NCTX]
    const float* __restrict__ roi,   // [BS,NSEQ,NBOX,NCTX]
    const int*   __restrict__ rcls,  // [BS,NBOX]
    const float* __restrict__ w,     // [BS,NSEQ,NBOX]
    const int*   __restrict__ pidx,  // [L,BS]
    const float* __restrict__ pval,  // [L,BS]
    const int*   __restrict__ cidx,  // [L,BS,MAXC]
    const float* __restrict__ cval,  // [L,BS,MAXC]
    const int*   __restrict__ eidx,  // [L,BS,MAXC]
    const int*   __restrict__ fsmp,  // [L,BS]
    const int*   __restrict__ fslt,  // [L,BS]
    float*       __restrict__ out,   // [BS,NSEQ,NBOX]
    int n_tasks, int L)
{
    const int gwarp = (blockIdx.x * blockDim.x + threadIdx.x) >> 5;
    const int lane  = threadIdx.x & 31;
    const int q3    = gwarp / 3;
    const int role  = gwarp - q3 * 3;

    if (role != 0) {
        // ---------------- copy warp: one per (b, r) row ----------------
        const int idx = q3 * 2 + (role - 1);
        if (idx >= BS * NSEQ) return;
        const int b = idx >> 5;          // / NSEQ
        const int r = idx & (NSEQ - 1);  // % NSEQ

        // is row r a valid parent at any iteration? (L <= 32)
        int   p = -1;
        float v = 0.f;
        if (lane < L) {
            p = pidx[lane * BS + b];
            v = pval[lane * BS + b];
        }
        const unsigned m =
            __ballot_sync(0xffffffffu, (lane < L) && (v > 0.f) && (p == r));
        if (m) return;  // compute warp owns this row

        const float4* src = (const float4*)(ent + ((size_t)b * NSEQ + r) * NBOX);
        float4*       dst = (float4*)(out + ((size_t)b * NSEQ + r) * NBOX);
        const float4 val = __ldcs(src + lane);
        __stcs(dst + lane, val);
        return;
    }

    // ---------------- compute warp: one per (it, b) task ----------------
    const int task = q3;
    if (task >= n_tasks) return;
    const int it = task >> 10;          // / BS
    const int b  = task & (BS - 1);     // % BS

    const int base = it * BS + b;
    const float pv = pval[base];
    if (pv <= 0.f) return;
    const int r = pidx[base];

    const int   c0  = cidx[base * MAXC + 0];
    const float cv0 = cval[base * MAXC + 0];
    const int   e0  = eidx[base * MAXC + 0];
    const int   fs  = fsmp[base];
    const int   fl  = fslt[base];
    const int   fe  = eidx[(it * BS + fs) * MAXC + fl];

    // --- transfer[k] = cv0 * sum_box ent[b,c0,box]*cls*spo[b,e0,box,k]*roi[b,e0,box,k] + 1e-6 ---
    const float* entc   = ent  + ((size_t)b * NSEQ + c0) * NBOX;
    const float* spor   = spo  + ((size_t)b * NSEQ + e0) * NBOX * NCTX;
    const float* roir   = roi  + ((size_t)b * NSEQ + e0) * NBOX * NCTX;
    const int*   clsrow = rcls + (size_t)b * NBOX;

    float t0 = 0.f, t1 = 0.f, t2 = 0.f, t3 = 0.f, t4 = 0.f;
    #pragma unroll
    for (int q = 0; q < NBOX / 32; q++) {
        const int box = lane + q * 32;
        float ca = entc[box];
        if (clsrow[box] == -1) ca = 0.f;
        const float* s  = spor + box * NCTX;
        const float* mr = roir + box * NCTX;
        t0 += ca * __ldcs(s + 0) * __ldcs(mr + 0);
        t1 += ca * __ldcs(s + 1) * __ldcs(mr + 1);
        t2 += ca * __ldcs(s + 2) * __ldcs(mr + 2);
        t3 += ca * __ldcs(s + 3) * __ldcs(mr + 3);
        t4 += ca * __ldcs(s + 4) * __ldcs(mr + 4);
    }
    #pragma unroll
    for (int o = 16; o > 0; o >>= 1) {
        t0 += __shfl_xor_sync(0xffffffffu, t0, o);
        t1 += __shfl_xor_sync(0xffffffffu, t1, o);
        t2 += __shfl_xor_sync(0xffffffffu, t2, o);
        t3 += __shfl_xor_sync(0xffffffffu, t3, o);
        t4 += __shfl_xor_sync(0xffffffffu, t4, o);
    }
    float tr[NCTX];
    tr[0] = cv0 * t0 + 1e-6f;
    tr[1] = cv0 * t1 + 1e-6f;
    tr[2] = cv0 * t2 + 1e-6f;
    tr[3] = cv0 * t3 + 1e-6f;
    tr[4] = cv0 * t4 + 1e-6f;

    // scatter columns: ctx_idx_adjusted[fs, fe, box=0, k] (uniform loads)
    int cols[NCTX];
    const int* cbase = ctx + (((size_t)fs * NSEQ + fe) * NBOX) * NCTX;
    #pragma unroll
    for (int k = 0; k < NCTX; k++) cols[k] = cbase[k];

    // --- row update: each lane owns 4 consecutive boxes of the parent row ---
    const float4 sub = ((const float4*)(ent + ((size_t)b * NSEQ + r) * NBOX))[lane];
    const float4 wv  = __ldcs(((const float4*)(w + ((size_t)b * NSEQ + r) * NBOX)) + lane);
    const int4   cl  = ((const int4*)clsrow)[lane];

    float su[4]  = {sub.x, sub.y, sub.z, sub.w};
    float wa[4]  = {wv.x, wv.y, wv.z, wv.w};
    int   cla[4] = {cl.x, cl.y, cl.z, cl.w};

    float u[4];
    float mx = 0.f;
    #pragma unroll
    for (int q = 0; q < 4; q++) {
        const int box = lane * 4 + q;
        float add = 1e-6f;
        #pragma unroll
        for (int k = 0; k < NCTX; k++)
            if (cols[k] == box) add = tr[k];
        u[q] = su[q] + add * wa[q];
        mx = fmaxf(mx, fabsf(u[q]));
    }
    #pragma unroll
    for (int o = 16; o > 0; o >>= 1)
        mx = fmaxf(mx, __shfl_xor_sync(0xffffffffu, mx, o));
    const float d = (mx <= 1.f) ? 1.f : mx;

    float rr[4];
    #pragma unroll
    for (int q = 0; q < 4; q++) {
        float vvv = u[q] / d;
        if (cla[q] == -1) vvv = -1.0f;
        rr[q] = vvv;
    }
    float4 res;
    res.x = rr[0]; res.y = rr[1]; res.z = rr[2]; res.w = rr[3];
    __stcs(((float4*)(out + ((size_t)b * NSEQ + r) * NBOX)) + lane, res);
}

extern "C" void kernel_launch(void* const* d_in, const int* in_sizes, int n_in,
                              void* d_out, int out_size) {
    const float* ent  = (const float*)d_in[0];   // ent_attn
    const float* spo  = (const float*)d_in[1];   // spo_attn
    const int*   ctx  = (const int*)  d_in[2];   // ctx_idx_adjusted
    const float* roi  = (const float*)d_in[3];   // roi_mask
    const int*   rcls = (const int*)  d_in[4];   // roi_cls
    const float* w    = (const float*)d_in[5];   // weight_on_children
    const int*   pidx = (const int*)  d_in[6];   // parent_idx [L,BS]
    const float* pval = (const float*)d_in[7];   // parent_valid
    const int*   cidx = (const int*)  d_in[8];   // child_idx
    const float* cval = (const float*)d_in[9];   // child_valid
    const int*   eidx = (const int*)  d_in[10];  // edge_idx
    const int*   fsmp = (const int*)  d_in[11];  // flat_sample
    const int*   fslt = (const int*)  d_in[12];  // flat_slot

    const int L = in_sizes[6] / BS;
    const int n_tasks = L * BS;

    // striped roles: 1 compute warp per 2 copy warps.
    const int n_copy = BS * NSEQ;                         // 32768 rows
    const int n_stripe = (n_tasks > (n_copy + 1) / 2) ? n_tasks : (n_copy + 1) / 2;
    const int total_warps = 3 * n_stripe;

    const int threads = 256;                              // 8 warps/block
    const int blocks = (total_warps * 32 + threads - 1) / threads;

    topdown_fused_kernel<<<blocks, threads>>>(
        ent, spo, ctx, roi, rcls, w,
        pidx, pval, cidx, cval, eidx, fsmp, fslt,
        (float*)d_out, n_tasks, L);
}

// round 13
// speedup vs baseline: 1.1931x; 1.0845x over previous
#include <cuda_runtime.h>
#include <cstdint>

// Problem constants (fixed by reference)
#define BS   1024
#define NSEQ 32
#define NBOX 128
#define NCTX 5
#define MAXC 4

// 384-thread blocks, intra-block role split:
//   warps 0-3  : compute task  bid*4 + wid      (one per (it,b), pval>0)
//   warps 4-11 : copy row      bid*8 + (wid-4)  (skip parent rows)
// Compute warps stage the 2560B spo and roi rows into shared memory with
// cp.async.cg (16B chunks, register-free MLP=20, L2-only caching), overlap
// the ent/cls/parent-row LDGs with the in-flight cp.asyncs, then reduce from
// smem (conflict-free: word index 5*lane+k, gcd(5,32)=1).
//
// Fully parallel: children always have larger indices than parents; parents
// ascend & are unique per batch, so every read in the sequential reference
// sees the ORIGINAL ent_attn. Parent rows are written only by compute warps,
// non-parent rows only by copy warps (exactly once each).
__global__ __launch_bounds__(384, 5) void topdown_fused_kernel(
    const float* __restrict__ ent,   // [BS,NSEQ,NBOX]
    const float* __restrict__ spo,   // [BS,NSEQ,NBOX,NCTX]
    const int*   __restrict__ ctx,   // [BS,NSEQ,NBOX,NCTX]
    const float* __restrict__ roi,   // [BS,NSEQ,NBOX,NCTX]
    const int*   __restrict__ rcls,  // [BS,NBOX]
    const float* __restrict__ w,     // [BS,NSEQ,NBOX]
    const int*   __restrict__ pidx,  // [L,BS]
    const float* __restrict__ pval,  // [L,BS]
    const int*   __restrict__ cidx,  // [L,BS,MAXC]
    const float* __restrict__ cval,  // [L,BS,MAXC]
    const int*   __restrict__ eidx,  // [L,BS,MAXC]
    const int*   __restrict__ fsmp,  // [L,BS]
    const int*   __restrict__ fslt,  // [L,BS]
    float*       __restrict__ out,   // [BS,NSEQ,NBOX]
    int n_tasks, int L)
{
    __shared__ alignas(16) float spoS[4][NBOX * NCTX];  // 4 x 2560B
    __shared__ alignas(16) float roiS[4][NBOX * NCTX];  // 4 x 2560B

    const int wid  = threadIdx.x >> 5;
    const int lane = threadIdx.x & 31;

    if (wid >= 4) {
        // ---------------- copy warp: one per (b, r) row ----------------
        const int idx = blockIdx.x * 8 + (wid - 4);
        if (idx >= BS * NSEQ) return;
        const int b = idx >> 5;          // / NSEQ
        const int r = idx & (NSEQ - 1);  // % NSEQ

        // is row r a valid parent at any iteration? (L <= 32)
        int   p = -1;
        float v = 0.f;
        if (lane < L) {
            p = pidx[lane * BS + b];
            v = pval[lane * BS + b];
        }
        const unsigned m =
            __ballot_sync(0xffffffffu, (lane < L) && (v > 0.f) && (p == r));
        if (m) return;  // compute warp owns this row

        const float4* src = (const float4*)(ent + ((size_t)b * NSEQ + r) * NBOX);
        float4*       dst = (float4*)(out + ((size_t)b * NSEQ + r) * NBOX);
        const float4 val = __ldcs(src + lane);
        __stcs(dst + lane, val);
        return;
    }

    // ---------------- compute warp: one per (it, b) task ----------------
    const int task = blockIdx.x * 4 + wid;
    if (task >= n_tasks) return;
    const int it = task >> 10;          // / BS
    const int b  = task & (BS - 1);     // % BS

    const int base = it * BS + b;
    const float pv = pval[base];
    if (pv <= 0.f) return;              // warp-uniform
    const int r = pidx[base];

    const int   c0  = cidx[base * MAXC + 0];
    const float cv0 = cval[base * MAXC + 0];
    const int   e0  = eidx[base * MAXC + 0];
    const int   fs  = fsmp[base];
    const int   fl  = fslt[base];
    const int   fe  = eidx[(it * BS + fs) * MAXC + fl];

    const float* spor = spo + ((size_t)b * NSEQ + e0) * NBOX * NCTX;
    const float* roir = roi + ((size_t)b * NSEQ + e0) * NBOX * NCTX;

    // --- stage both rows into smem: 10 register-free 512B bulk copies ---
    #pragma unroll
    for (int j = 0; j < 5; j++) {
        const int c = (j * 32 + lane) * 4;   // float index of 16B chunk
        const uint32_t ds = (uint32_t)__cvta_generic_to_shared(&spoS[wid][c]);
        asm volatile("cp.async.cg.shared.global [%0], [%1], 16;\n"
                     :: "r"(ds), "l"(spor + c));
        const uint32_t dr = (uint32_t)__cvta_generic_to_shared(&roiS[wid][c]);
        asm volatile("cp.async.cg.shared.global [%0], [%1], 16;\n"
                     :: "r"(dr), "l"(roir + c));
    }
    asm volatile("cp.async.commit_group;\n" ::: "memory");

    // --- overlap: ent child row, cls, parent row, weights, ctx cols ---
    const float* entc   = ent  + ((size_t)b * NSEQ + c0) * NBOX;
    const int*   clsrow = rcls + (size_t)b * NBOX;

    float caq[4];
    #pragma unroll
    for (int q = 0; q < 4; q++) {
        const int box = lane + q * 32;
        const float e = entc[box];
        caq[q] = (clsrow[box] == -1) ? 0.f : e;
    }

    int cols[NCTX];
    const int* cbase = ctx + (((size_t)fs * NSEQ + fe) * NBOX) * NCTX;
    #pragma unroll
    for (int k = 0; k < NCTX; k++) cols[k] = cbase[k];

    const float4 sub = ((const float4*)(ent + ((size_t)b * NSEQ + r) * NBOX))[lane];
    const float4 wv  = __ldcs(((const float4*)(w + ((size_t)b * NSEQ + r) * NBOX)) + lane);
    const int4   cl  = ((const int4*)clsrow)[lane];

    // --- wait for staged rows, then conflict-free smem reduction ---
    asm volatile("cp.async.wait_group 0;\n" ::: "memory");
    __syncwarp();

    float t0 = 0.f, t1 = 0.f, t2 = 0.f, t3 = 0.f, t4 = 0.f;
    #pragma unroll
    for (int q = 0; q < 4; q++) {
        const int box = lane + q * 32;
        const float ca = caq[q];
        const float* s  = &spoS[wid][box * NCTX];
        const float* mr = &roiS[wid][box * NCTX];
        t0 += ca * s[0] * mr[0];
        t1 += ca * s[1] * mr[1];
        t2 += ca * s[2] * mr[2];
        t3 += ca * s[3] * mr[3];
        t4 += ca * s[4] * mr[4];
    }
    #pragma unroll
    for (int o = 16; o > 0; o >>= 1) {
        t0 += __shfl_xor_sync(0xffffffffu, t0, o);
        t1 += __shfl_xor_sync(0xffffffffu, t1, o);
        t2 += __shfl_xor_sync(0xffffffffu, t2, o);
        t3 += __shfl_xor_sync(0xffffffffu, t3, o);
        t4 += __shfl_xor_sync(0xffffffffu, t4, o);
    }
    float tr[NCTX];
    tr[0] = cv0 * t0 + 1e-6f;
    tr[1] = cv0 * t1 + 1e-6f;
    tr[2] = cv0 * t2 + 1e-6f;
    tr[3] = cv0 * t3 + 1e-6f;
    tr[4] = cv0 * t4 + 1e-6f;

    // --- row update: each lane owns 4 consecutive boxes of the parent row ---
    float su[4]  = {sub.x, sub.y, sub.z, sub.w};
    float wa[4]  = {wv.x, wv.y, wv.z, wv.w};
    int   cla[4] = {cl.x, cl.y, cl.z, cl.w};

    float u[4];
    float mx = 0.f;
    #pragma unroll
    for (int q = 0; q < 4; q++) {
        const int box = lane * 4 + q;
        float add = 1e-6f;
        #pragma unroll
        for (int k = 0; k < NCTX; k++)
            if (cols[k] == box) add = tr[k];
        u[q] = su[q] + add * wa[q];
        mx = fmaxf(mx, fabsf(u[q]));
    }
    #pragma unroll
    for (int o = 16; o > 0; o >>= 1)
        mx = fmaxf(mx, __shfl_xor_sync(0xffffffffu, mx, o));
    const float d = (mx <= 1.f) ? 1.f : mx;

    float rr[4];
    #pragma unroll
    for (int q = 0; q < 4; q++) {
        float vvv = u[q] / d;
        if (cla[q] == -1) vvv = -1.0f;
        rr[q] = vvv;
    }
    float4 res;
    res.x = rr[0]; res.y = rr[1]; res.z = rr[2]; res.w = rr[3];
    __stcs(((float4*)(out + ((size_t)b * NSEQ + r) * NBOX)) + lane, res);
}

extern "C" void kernel_launch(void* const* d_in, const int* in_sizes, int n_in,
                              void* d_out, int out_size) {
    const float* ent  = (const float*)d_in[0];   // ent_attn
    const float* spo  = (const float*)d_in[1];   // spo_attn
    const int*   ctx  = (const int*)  d_in[2];   // ctx_idx_adjusted
    const float* roi  = (const float*)d_in[3];   // roi_mask
    const int*   rcls = (const int*)  d_in[4];   // roi_cls
    const float* w    = (const float*)d_in[5];   // weight_on_children
    const int*   pidx = (const int*)  d_in[6];   // parent_idx [L,BS]
    const float* pval = (const float*)d_in[7];   // parent_valid
    const int*   cidx = (const int*)  d_in[8];   // child_idx
    const float* cval = (const float*)d_in[9];   // child_valid
    const int*   eidx = (const int*)  d_in[10];  // edge_idx
    const int*   fsmp = (const int*)  d_in[11];  // flat_sample
    const int*   fslt = (const int*)  d_in[12];  // flat_slot

    const int L = in_sizes[6] / BS;
    const int n_tasks = L * BS;

    // 4 compute warps + 8 copy warps per 384-thread block
    const int blocks_compute = (n_tasks + 3) / 4;
    const int blocks_copy    = (BS * NSEQ + 7) / 8;     // 4096
    const int blocks = blocks_compute > blocks_copy ? blocks_compute : blocks_copy;

    topdown_fused_kernel<<<blocks, 384>>>(
        ent, spo, ctx, roi, rcls, w,
        pidx, pval, cidx, cval, eidx, fsmp, fslt,
        (float*)d_out, n_tasks, L);
}